// round 3
// baseline (speedup 1.0000x reference)
#include <cuda_runtime.h>
#include <cstdint>

#define NW 14
#define NSTATE (1 << NW)        // 16384 amplitudes
#define NLAYERS 6               // (DEPTH+1) * SEL_LAYERS
#define NTHREADS 512
#define NPARAMS (2 * NW * 3)    // 84

// ---------------------------------------------------------------------------
// Compile-time GF(2) algebra: lazy CNOT permutation tracking.
// Storage invariant: psi[x] = a[T * x] (T invertible 14x14 over GF(2)).
// CNOT layer with range r maps psi'[y] = psi[Q y], Q = C_0 C_1 ... C_13,
// so T' = T*Q, Tinv' = Qinv*Tinv.  Rot on wire w pairs physical (j, j^v),
// v = col_w(T); role parity = <row_w(Tinv), j>.
// A linear swizzle sw(j) = j ^ (j>>4) ^ (j>>9) is folded into offsets for
// shared-memory bank spreading (linearity: sw(j^o) = sw(j)^sw(o)).
// ---------------------------------------------------------------------------

struct GroupTab {
    int      piv[4];     // sorted pivot bit positions for coset enumeration
    uint16_t offs[16];   // PRE-SWIZZLED xor-offsets of the 2^g coset members
    uint16_t umask[4];   // role-parity masks (rows of Tinv)
    uint8_t  uidx[4];    // index into U-matrix table: l*NW + w
};
struct Tables {
    GroupTab grp[NLAYERS][4];
    uint16_t zu[NW];     // final Tinv rows -> measurement sign masks
};

__host__ __device__ constexpr unsigned swz(unsigned j) {
    return j ^ (j >> 4) ^ (j >> 9);
}

constexpr Tables build_tables() {
    Tables t{};
    const int GSIZE[4]  = {4, 4, 3, 3};
    const int GSTART[4] = {0, 4, 8, 11};
    uint16_t Tcol[NW]  = {};
    uint16_t TiRow[NW] = {};
    for (int i = 0; i < NW; i++) { Tcol[i] = (uint16_t)(1u << i); TiRow[i] = (uint16_t)(1u << i); }

    for (int L = 0; L < NLAYERS; L++) {
        int l = L & 1;
        for (int g = 0; g < 4; g++) {
            GroupTab& G = t.grp[L][g];
            int gs = GSIZE[g], w0 = GSTART[g];
            uint16_t v[4] = {0, 0, 0, 0};
            for (int i = 0; i < gs; i++) {
                v[i]       = Tcol[w0 + i];
                G.umask[i] = TiRow[w0 + i];
                G.uidx[i]  = (uint8_t)(l * NW + w0 + i);
            }
            for (int i = gs; i < 4; i++) { G.umask[i] = 0; G.uidx[i] = 0; }
            for (int m = 0; m < (1 << gs); m++) {
                uint16_t o = 0;
                for (int i = 0; i < gs; i++) if ((m >> i) & 1) o = (uint16_t)(o ^ v[i]);
                G.offs[m] = (uint16_t)swz(o);          // pre-swizzled
            }
            for (int m = (1 << gs); m < 16; m++) G.offs[m] = 0;
            // Gauss-Jordan pivots (canonical coset representatives)
            uint16_t red[4] = {};
            for (int i = 0; i < 4; i++) red[i] = (i < gs) ? v[i] : (uint16_t)0;
            int piv[4] = {0, 0, 0, 0};
            for (int i = 0; i < gs; i++) {
                int p = 0; while (((red[i] >> p) & 1) == 0) p++;
                piv[i] = p;
                for (int jj = 0; jj < gs; jj++)
                    if (jj != i && ((red[jj] >> p) & 1)) red[jj] = (uint16_t)(red[jj] ^ red[i]);
            }
            for (int a = 0; a < gs; a++)
                for (int b2 = a + 1; b2 < gs; b2++)
                    if (piv[b2] < piv[a]) { int tmp = piv[a]; piv[a] = piv[b2]; piv[b2] = tmp; }
            for (int i = 0; i < gs; i++) G.piv[i] = piv[i];
            for (int i = gs; i < 4; i++) G.piv[i] = 13;   // unused (inserts high zero bit; never reached)
        }
        // CNOT ring layer, range r = (L%2)+1
        int r = l + 1;
        uint16_t Qrow[NW]  = {};
        uint16_t QiRow[NW] = {};
        for (int i = 0; i < NW; i++) { Qrow[i] = (uint16_t)(1u << i); QiRow[i] = (uint16_t)(1u << i); }
        for (int w = NW - 1; w >= 0; w--) Qrow[(w + r) % NW]  = (uint16_t)(Qrow[(w + r) % NW]  ^ Qrow[w]);
        for (int w = 0; w < NW; w++)      QiRow[(w + r) % NW] = (uint16_t)(QiRow[(w + r) % NW] ^ QiRow[w]);
        uint16_t nT[NW]  = {};
        uint16_t nTi[NW] = {};
        for (int w = 0; w < NW; w++) {                      // T' = T*Q (columns)
            uint16_t c = 0;
            for (int i = 0; i < NW; i++) if ((Qrow[i] >> w) & 1) c = (uint16_t)(c ^ Tcol[i]);
            nT[w] = c;
        }
        for (int i = 0; i < NW; i++) {                      // Tinv' = Qinv*Tinv (rows)
            uint16_t rr = 0;
            for (int k = 0; k < NW; k++) if ((QiRow[i] >> k) & 1) rr = (uint16_t)(rr ^ TiRow[k]);
            nTi[i] = rr;
        }
        for (int i = 0; i < NW; i++) { Tcol[i] = nT[i]; TiRow[i] = nTi[i]; }
    }
    for (int i = 0; i < NW; i++) t.zu[i] = TiRow[i];
    return t;
}

__constant__ Tables TAB = build_tables();

// ---------------------------------------------------------------------------
// Fused multi-gate sweep: each thread owns one (or more) cosets of 2^G
// amplitudes, applies G commuting single-qubit Rot gates in registers.
// ---------------------------------------------------------------------------
template <int G>
__device__ __forceinline__ void sweep(float2* __restrict__ st,
                                      const GroupTab& gt,
                                      const float2* __restrict__ Us) {
    float2 u[G][4];
#pragma unroll
    for (int i = 0; i < G; i++) {
        int base = (int)gt.uidx[i] * 4;
#pragma unroll
        for (int e = 0; e < 4; e++) u[i][e] = Us[base + e];
    }
    int piv[G]; unsigned um[G];
#pragma unroll
    for (int i = 0; i < G; i++) { piv[i] = gt.piv[i]; um[i] = gt.umask[i]; }
    unsigned offs[1 << G];
#pragma unroll
    for (int m = 0; m < (1 << G); m++) offs[m] = gt.offs[m];

    const int NG = NSTATE >> G;
    for (int kg = threadIdx.x; kg < NG; kg += NTHREADS) {
        unsigned j = (unsigned)kg;
#pragma unroll
        for (int i = 0; i < G; i++) {                     // insert 0 at pivot bits (ascending)
            unsigned lowmask = (1u << piv[i]) - 1u;
            j = ((j & ~lowmask) << 1) | (j & lowmask);
        }
        unsigned sj = swz(j);
        float2 a[1 << G];
#pragma unroll
        for (int m = 0; m < (1 << G); m++) a[m] = st[sj ^ offs[m]];
#pragma unroll
        for (int i = 0; i < G; i++) {
            unsigned bb = __popc(j & um[i]) & 1u;         // logical-role parity of coset rep
            float2 w00 = bb ? u[i][3] : u[i][0];
            float2 w01 = bb ? u[i][2] : u[i][1];
            float2 w10 = bb ? u[i][1] : u[i][2];
            float2 w11 = bb ? u[i][0] : u[i][3];
#pragma unroll
            for (int m = 0; m < (1 << G); m++) {
                if (m & (1 << i)) continue;
                float2 a0 = a[m], a1 = a[m | (1 << i)];
                float2 n0, n1;
                n0.x = w00.x * a0.x - w00.y * a0.y + w01.x * a1.x - w01.y * a1.y;
                n0.y = w00.x * a0.y + w00.y * a0.x + w01.x * a1.y + w01.y * a1.x;
                n1.x = w10.x * a0.x - w10.y * a0.y + w11.x * a1.x - w11.y * a1.y;
                n1.y = w10.x * a0.y + w10.y * a0.x + w11.x * a1.y + w11.y * a1.x;
                a[m] = n0; a[m | (1 << i)] = n1;
            }
        }
#pragma unroll
        for (int m = 0; m < (1 << G); m++) st[sj ^ offs[m]] = a[m];
    }
}

__global__ void __launch_bounds__(NTHREADS, 1)
qsim_kernel(const float* __restrict__ state_batch,
            const float* __restrict__ params,
            const float* __restrict__ head_w,
            const float* __restrict__ head_b,
            float* __restrict__ out) {
    extern __shared__ float2 st[];                 // 16384 x 8B = 128 KB
    __shared__ float2 Usm[2 * NW * 4];             // 28 Rot matrices
    __shared__ float  redsm[16 * NW];

    const int b   = blockIdx.x;
    const int tid = threadIdx.x;

    // zero state
    for (int i = tid; i < NSTATE; i += NTHREADS) st[i] = make_float2(0.f, 0.f);

    // 28 distinct Rot matrices (weights shared across the 3 blocks)
    if (tid < 2 * NW) {
        const float* p = params + (size_t)b * NPARAMS + tid * 3;
        float phi = p[0], th = p[1], om = p[2];
        float s, c;  sincosf(0.5f * th, &s, &c);
        float sa, ca; sincosf(0.5f * (phi + om), &sa, &ca);
        float sb, cb; sincosf(0.5f * (phi - om), &sb, &cb);
        float2* U = &Usm[tid * 4];
        U[0] = make_float2( ca * c, -sa * c);   // u00 = e^{-i(phi+om)/2} cos
        U[1] = make_float2(-cb * s, -sb * s);   // u01 = -e^{+i(phi-om)/2} sin
        U[2] = make_float2( cb * s, -sb * s);   // u10 =  e^{-i(phi-om)/2} sin
        U[3] = make_float2( ca * c,  sa * c);   // u11 = e^{+i(phi+om)/2} cos
    }
    __syncthreads();

    // AngleEmbedding: RX(0 or pi) -> basis state (global phase irrelevant)
    if (tid == 0) {
        unsigned j0 = 0;
        const float* sb_ = state_batch + (size_t)b * (NSTATE * 2);
        for (int w = 0; w < NW; w++) if (sb_[w] < 0.f) j0 |= (1u << w);
        st[swz(j0)] = make_float2(1.f, 0.f);
    }
    __syncthreads();

    // 6 layers: 14 Rots each (fused 4+4+3+3); CNOT layers are free (in TAB)
    for (int L = 0; L < NLAYERS; L++) {
        sweep<4>(st, TAB.grp[L][0], Usm); __syncthreads();
        sweep<4>(st, TAB.grp[L][1], Usm); __syncthreads();
        sweep<3>(st, TAB.grp[L][2], Usm); __syncthreads();
        sweep<3>(st, TAB.grp[L][3], Usm); __syncthreads();
    }

    // <Z_w> via final Tinv sign masks, then linear head
    unsigned zu[NW];
#pragma unroll
    for (int w = 0; w < NW; w++) zu[w] = TAB.zu[w];
    float acc[NW];
#pragma unroll
    for (int w = 0; w < NW; w++) acc[w] = 0.f;
    for (int j = tid; j < NSTATE; j += NTHREADS) {
        float2 a = st[swz((unsigned)j)];
        float pv = a.x * a.x + a.y * a.y;
        unsigned pb = __float_as_uint(pv);
#pragma unroll
        for (int w = 0; w < NW; w++) {
            unsigned s = (__popc((unsigned)j & zu[w]) & 1u) << 31;
            acc[w] += __uint_as_float(pb ^ s);
        }
    }
#pragma unroll
    for (int w = 0; w < NW; w++) {
#pragma unroll
        for (int o = 16; o > 0; o >>= 1) acc[w] += __shfl_xor_sync(0xffffffffu, acc[w], o);
    }
    const int lane = tid & 31, warp = tid >> 5;
    if (lane == 0) {
#pragma unroll
        for (int w = 0; w < NW; w++) redsm[warp * NW + w] = acc[w];
    }
    __syncthreads();
    if (tid == 0) {
        float r_ = head_b[0];
#pragma unroll
        for (int w = 0; w < NW; w++) {
            float z = 0.f;
            for (int k = 0; k < 16; k++) z += redsm[k * NW + w];
            r_ += z * head_w[w];
        }
        out[b] = r_;
    }
}

extern "C" void kernel_launch(void* const* d_in, const int* in_sizes, int n_in,
                              void* d_out, int out_size) {
    const float* state_batch = (const float*)d_in[0];
    const float* params      = (const float*)d_in[1];
    const float* head_w      = (const float*)d_in[2];
    const float* head_b      = (const float*)d_in[3];
    float* out = (float*)d_out;

    int B = in_sizes[0] / (NSTATE * 2);   // 512
    cudaFuncSetAttribute(qsim_kernel, cudaFuncAttributeMaxDynamicSharedMemorySize,
                         NSTATE * (int)sizeof(float2));
    qsim_kernel<<<B, NTHREADS, NSTATE * sizeof(float2)>>>(state_batch, params, head_w, head_b, out);
}